// round 13
// baseline (speedup 1.0000x reference)
#include <cuda_runtime.h>
#include <cuda_fp16.h>
#include <cstdint>

// ---------------------------------------------------------------------------
// SparseMPNNLayer — factorized edge MLP on mma.sync m16n8k16 fp16.
//   GEMM1 factorization:  [A[src]|B[dst]|ef] @ W1
//        = (A@W1a+b1)[src] + (B@W1b)[dst] + ef@W1c
//   The node-level parts are precomputed once (pre_mlp, fp16 tables),
//   so the per-edge GEMM1 runs with K=64 instead of K=192.
// ---------------------------------------------------------------------------

#define NTPB 256
#define ETPB 256
#define PTPB 256
constexpr int HD = 64;
constexpr int MAXN = 100000;

__device__ float    g_m_u[(size_t)MAXN * HD];
__device__ float    g_m_v[(size_t)MAXN * HD];
__device__ float    g_deg[MAXN];
__device__ uint32_t g_PA[(size_t)MAXN * 64];   // [N][128 halves] = 64 words
__device__ uint32_t g_PB[(size_t)MAXN * 64];

// ---- edge smem layout (words) ---------------------------------------------
constexpr int EW1_OFF = 0;                     // W1c  [128 n][64 k]h  (4096 w)
constexpr int EW2_OFF = EW1_OFF + 128 * 32;    // W2   [64 n][128 k]h  (4096 w)
constexpr int EX_OFF  = EW2_OFF + 64 * 64;     // ef   [128 e][64 k]h  (4096 w)
constexpr int EH_OFF  = EX_OFF + 128 * 32;     // H    [128 e][128 h]h (8192 w)
constexpr int EB2_OFF = EH_OFF + 128 * 64;     // 64 f32
constexpr int EDGE_SMEM = (EB2_OFF + 64) * 4;  // 82176 B

// ---- node smem layout (words) ---------------------------------------------
constexpr int NW1_OFF = 0;                     // [64 n][128 k]h
constexpr int NW2_OFF = NW1_OFF + 64 * 64;     // [64 n][64 k]h
constexpr int NX_OFF  = NW2_OFF + 64 * 32;     // [128 r][128 k]h
constexpr int NH_OFF  = NX_OFF + 128 * 64;     // [128 r][64 h]h
constexpr int NB1_OFF = NH_OFF + 128 * 32;     // 64 f32
constexpr int NB2_OFF = NB1_OFF + 64;          // 64 f32
constexpr int NODE_SMEM = (NB2_OFF + 64) * 4;  // 74240 B

// ---- pre smem layout (words) ----------------------------------------------
constexpr int PW_OFF  = 0;                     // [128 n][64 k]h (4096 w)
constexpr int PX_OFF  = PW_OFF + 128 * 32;     // [128 r][64 k]h (4096 w)
constexpr int PB_OFF  = PX_OFF + 128 * 32;     // 128 f32
constexpr int PRE_SMEM = (PB_OFF + 128) * 4;   // 33280 B

__device__ __forceinline__ uint32_t p2h(float a, float b) {
    __half2 h = __floats2half2_rn(a, b);   // low = a
    return *(uint32_t*)&h;
}
__device__ __forceinline__ uint4 pack8(float4 a, float4 b) {
    uint4 r;
    r.x = p2h(a.x, a.y); r.y = p2h(a.z, a.w);
    r.z = p2h(b.x, b.y); r.w = p2h(b.z, b.w);
    return r;
}

__device__ __forceinline__ void mma16(float* c, uint32_t a0, uint32_t a1,
                                      uint32_t a2, uint32_t a3,
                                      uint32_t b0, uint32_t b1) {
    asm("mma.sync.aligned.m16n8k16.row.col.f32.f16.f16.f32 "
        "{%0,%1,%2,%3}, {%4,%5,%6,%7}, {%8,%9}, {%0,%1,%2,%3};"
        : "+f"(c[0]), "+f"(c[1]), "+f"(c[2]), "+f"(c[3])
        : "r"(a0), "r"(a1), "r"(a2), "r"(a3), "r"(b0), "r"(b1));
}

// XOR-swizzled 16B-chunk store: row stride in words, chunk = 16B unit index.
__device__ __forceinline__ void st_chunk(uint32_t* b, int row, int stride,
                                         int chunk, uint4 v) {
    const int c = (chunk & ~7) | ((chunk & 7) ^ (row & 7));
    *(uint4*)(b + row * stride + c * 4) = v;
}

// ---------------------------------------------------------------------------
// pre_mlp: OUT[i][0:128]h = X[i][0:64] @ W[64][128] (+ bias)
// Tile = 128 rows, 8 warps, warp = 32r x 64c, K=64. 2 CTAs/SM.
// ---------------------------------------------------------------------------
__global__ void __launch_bounds__(PTPB, 2) pre_mlp(
    const float* __restrict__ X, const float* __restrict__ W,
    const float* __restrict__ bias, uint32_t* __restrict__ OUT, int N)
{
    extern __shared__ uint32_t smu[];
    uint32_t* Ws = smu + PW_OFF;
    uint32_t* Xs = smu + PX_OFF;
    float* sB = (float*)(smu + PB_OFF);

    const int tid = threadIdx.x;
    const int warp = tid >> 5, lane = tid & 31;
    const int g = lane >> 2, t = lane & 3;

    for (int i = tid; i < 32 * 128; i += PTPB) {
        const int kp = i >> 7, n = i & 127;
        const int ch = kp >> 2;
        const int cc = (ch & ~7) | ((ch & 7) ^ (n & 7));
        Ws[n * 32 + cc * 4 + (kp & 3)] =
            p2h(W[(2 * kp) * 128 + n], W[(2 * kp + 1) * 128 + n]);
    }
    if (tid < 128) sB[tid] = (bias != nullptr) ? bias[tid] : 0.0f;
    __syncthreads();

    int off3[8];
    #pragma unroll
    for (int c = 0; c < 8; c++) off3[c] = ((c ^ g) << 2) + t;

    const int m0 = (warp >> 1) * 32;
    const int n0 = (warp & 1) * 64;

    int arX[2][2], brB[8];
    #pragma unroll
    for (int mi = 0; mi < 2; mi++) {
        arX[mi][0] = (m0 + mi * 16 + g) * 32;
        arX[mi][1] = (m0 + mi * 16 + g + 8) * 32;
    }
    #pragma unroll
    for (int ni = 0; ni < 8; ni++) brB[ni] = (n0 + ni * 8 + g) * 32;

    const int sr = tid >> 1, half = tid & 1;
    const int ntiles = (N + 127) >> 7;

    for (int tile = blockIdx.x; tile < ntiles; tile += gridDim.x) {
        const int base = tile << 7;
        {
            const int i = base + sr;
            if (i < N) {
                const float4* s = (const float4*)(X + (size_t)i * HD);
                #pragma unroll
                for (int j = 0; j < 4; j++) {
                    const int c = half * 4 + j;
                    st_chunk(Xs, sr, 32, c, pack8(s[2 * c], s[2 * c + 1]));
                }
            }
        }
        __syncthreads();

        float c1[2][8][4];
        #pragma unroll
        for (int mi = 0; mi < 2; mi++)
            #pragma unroll
            for (int ni = 0; ni < 8; ni++)
                #pragma unroll
                for (int p = 0; p < 4; p++) c1[mi][ni][p] = 0.0f;

        #pragma unroll
        for (int ks = 0; ks < 4; ks++) {
            const int C0 = 2 * ks, C1 = 2 * ks + 1;
            const int o0 = ((C0 & ~7) << 2) + off3[C0 & 7];
            const int o1 = ((C1 & ~7) << 2) + off3[C1 & 7];
            uint32_t a[2][4];
            #pragma unroll
            for (int mi = 0; mi < 2; mi++) {
                a[mi][0] = Xs[arX[mi][0] + o0];
                a[mi][1] = Xs[arX[mi][1] + o0];
                a[mi][2] = Xs[arX[mi][0] + o1];
                a[mi][3] = Xs[arX[mi][1] + o1];
            }
            #pragma unroll
            for (int ni = 0; ni < 8; ni++)
                #pragma unroll
                for (int mi = 0; mi < 2; mi++)
                    mma16(c1[mi][ni], a[mi][0], a[mi][1], a[mi][2], a[mi][3],
                          Ws[brB[ni] + o0], Ws[brB[ni] + o1]);
        }

        #pragma unroll
        for (int mi = 0; mi < 2; mi++) {
            const int gi0 = base + m0 + mi * 16 + g, gi1 = gi0 + 8;
            #pragma unroll
            for (int ni = 0; ni < 8; ni++) {
                const int col = n0 + ni * 8 + 2 * t;
                const float2 bb = *(const float2*)(sB + col);
                const int w = (col >> 1);
                if (gi0 < N)
                    OUT[(size_t)gi0 * 64 + w] =
                        p2h(c1[mi][ni][0] + bb.x, c1[mi][ni][1] + bb.y);
                if (gi1 < N)
                    OUT[(size_t)gi1 * 64 + w] =
                        p2h(c1[mi][ni][2] + bb.x, c1[mi][ni][3] + bb.y);
            }
        }
        __syncthreads();   // X reads done before next stage
    }
}

// ---------------------------------------------------------------------------
// Edge MLP (factorized):
//   pre1 = PA[idxA[e]] + PB[idxB[e]] + ef@W1c     (PA carries +b1)
//   msg  = relu(pre1) @ W2 + b2 -> atomicAdd accum[idxOut[e]]
// Tile = 128 edges, 8 warps, 1 CTA/SM.
// ---------------------------------------------------------------------------
__global__ void __launch_bounds__(ETPB, 1) edge_mlp_tc(
    const uint32_t* __restrict__ PA, const int* __restrict__ idxA,
    const uint32_t* __restrict__ PB, const int* __restrict__ idxB,
    const float* __restrict__ EF, const int* __restrict__ idxOut,
    const float* __restrict__ W1c, const float* __restrict__ W2,
    const float* __restrict__ b2,
    float* __restrict__ accum, float* __restrict__ deg, int E)
{
    extern __shared__ uint32_t smu[];
    uint32_t* W1s = smu + EW1_OFF;
    uint32_t* W2s = smu + EW2_OFF;
    uint32_t* Xs  = smu + EX_OFF;
    uint32_t* Hs  = smu + EH_OFF;
    float* sB2 = (float*)(smu + EB2_OFF);

    const int tid = threadIdx.x;
    const int warp = tid >> 5, lane = tid & 31;
    const int g = lane >> 2, t = lane & 3;

    // ---- one-time: weights -> [n][k] halves, swizzled ---------------------
    for (int i = tid; i < 32 * 128; i += ETPB) {
        const int kp = i >> 7, n = i & 127;
        const int ch = kp >> 2;
        const int cc = (ch & ~7) | ((ch & 7) ^ (n & 7));
        W1s[n * 32 + cc * 4 + (kp & 3)] =
            p2h(W1c[(2 * kp) * 128 + n], W1c[(2 * kp + 1) * 128 + n]);
    }
    for (int i = tid; i < 64 * 64; i += ETPB) {
        const int kp = i >> 6, n = i & 63;
        const int ch = kp >> 2;
        const int cc = (ch & ~7) | ((ch & 7) ^ (n & 7));
        W2s[n * 64 + cc * 4 + (kp & 3)] =
            p2h(W2[(2 * kp) * 64 + n], W2[(2 * kp + 1) * 64 + n]);
    }
    if (tid < 64) sB2[tid] = b2[tid];

    int off3[8];
    #pragma unroll
    for (int c = 0; c < 8; c++) off3[c] = ((c ^ g) << 2) + t;

    const int m0 = (warp >> 1) * 32;
    const int n0 = (warp & 1) * 64;
    const int nb = (warp & 1) * 32;

    int arA[2][2], arH[2][2], brB[8], br2[4];
    #pragma unroll
    for (int mi = 0; mi < 2; mi++) {
        arA[mi][0] = (m0 + mi * 16 + g) * 32;
        arA[mi][1] = (m0 + mi * 16 + g + 8) * 32;
        arH[mi][0] = (m0 + mi * 16 + g) * 64;
        arH[mi][1] = (m0 + mi * 16 + g + 8) * 64;
    }
    #pragma unroll
    for (int ni = 0; ni < 8; ni++) brB[ni] = (n0 + ni * 8 + g) * 32;
    #pragma unroll
    for (int ni = 0; ni < 4; ni++) br2[ni] = (nb + ni * 8 + g) * 64;

    const int sr = tid >> 1, half = tid & 1;
    const int ntiles = (E + 127) >> 7;

    for (int tile = blockIdx.x; tile < ntiles; tile += gridDim.x) {
        const int base = tile << 7;

        // ---- fragment gather: PA[idxA]+PB[idxB] as half2 (latency-hidden) -
        uint32_t gth[4][8];
        #pragma unroll
        for (int r = 0; r < 4; r++) {
            const int row = m0 + (r >> 1) * 16 + (r & 1) * 8 + g;
            const int ge = base + row;
            if (ge < E) {
                const uint32_t* pa = PA + (size_t)idxA[ge] * 64 + (n0 >> 1) + t;
                const uint32_t* pb = PB + (size_t)idxB[ge] * 64 + (n0 >> 1) + t;
                #pragma unroll
                for (int ni = 0; ni < 8; ni++) {
                    __half2 s = __hadd2(*(const __half2*)(pa + ni * 4),
                                        *(const __half2*)(pb + ni * 4));
                    gth[r][ni] = *(uint32_t*)&s;
                }
            } else {
                #pragma unroll
                for (int ni = 0; ni < 8; ni++) gth[r][ni] = 0;
            }
        }

        // ---- stage ef [128 rows][8 chunks], coalesced -----------------
        {
            const int ge = base + sr;
            if (ge < E) {
                const float4* s = (const float4*)(EF + (size_t)ge * HD);
                #pragma unroll
                for (int j = 0; j < 4; j++) {
                    const int c = half * 4 + j;
                    st_chunk(Xs, sr, 32, c, pack8(s[2 * c], s[2 * c + 1]));
                }
            }
        }
        __syncthreads();   // (1) Xs ready (also covers weight staging)

        // ---- GEMM1': 32e x 64h, K=64 (4 k16 steps) ----
        float c1[2][8][4];
        #pragma unroll
        for (int mi = 0; mi < 2; mi++)
            #pragma unroll
            for (int ni = 0; ni < 8; ni++)
                #pragma unroll
                for (int p = 0; p < 4; p++) c1[mi][ni][p] = 0.0f;

        #pragma unroll
        for (int ks = 0; ks < 4; ks++) {
            const int C0 = 2 * ks, C1 = 2 * ks + 1;
            const int o0 = ((C0 & ~7) << 2) + off3[C0 & 7];
            const int o1 = ((C1 & ~7) << 2) + off3[C1 & 7];
            uint32_t a[2][4];
            #pragma unroll
            for (int mi = 0; mi < 2; mi++) {
                a[mi][0] = Xs[arA[mi][0] + o0];
                a[mi][1] = Xs[arA[mi][1] + o0];
                a[mi][2] = Xs[arA[mi][0] + o1];
                a[mi][3] = Xs[arA[mi][1] + o1];
            }
            #pragma unroll
            for (int ni = 0; ni < 8; ni++)
                #pragma unroll
                for (int mi = 0; mi < 2; mi++)
                    mma16(c1[mi][ni], a[mi][0], a[mi][1], a[mi][2], a[mi][3],
                          W1s[brB[ni] + o0], W1s[brB[ni] + o1]);
        }

        // ---- epilogue 1: relu(c1 + gathered) -> H (fp16, swizzled) ----
        #pragma unroll
        for (int mi = 0; mi < 2; mi++) {
            const int r0 = m0 + mi * 16 + g;
            #pragma unroll
            for (int ni = 0; ni < 8; ni++) {
                const __half2 g0 = *(__half2*)&gth[2 * mi][ni];
                const __half2 g1 = *(__half2*)&gth[2 * mi + 1][ni];
                const int ch = (n0 >> 3) + ni;
                const int cc = (ch & ~7) | ((ch & 7) ^ g);
                const int wo = cc * 4 + t;
                Hs[r0 * 64 + wo] =
                    p2h(fmaxf(c1[mi][ni][0] + __low2float(g0), 0.0f),
                        fmaxf(c1[mi][ni][1] + __high2float(g0), 0.0f));
                Hs[(r0 + 8) * 64 + wo] =
                    p2h(fmaxf(c1[mi][ni][2] + __low2float(g1), 0.0f),
                        fmaxf(c1[mi][ni][3] + __high2float(g1), 0.0f));
            }
        }
        if (deg != nullptr && tid < 128) {
            const int ge = base + tid;
            if (ge < E) atomicAdd(deg + idxA[ge], 1.0f);
        }
        __syncthreads();   // (2) H ready (Xs reads done)

        // ---- GEMM2: 32e x 32o, K=128 (8 k16 steps) ----
        float c2[2][4][4];
        #pragma unroll
        for (int mi = 0; mi < 2; mi++)
            #pragma unroll
            for (int ni = 0; ni < 4; ni++)
                #pragma unroll
                for (int p = 0; p < 4; p++) c2[mi][ni][p] = 0.0f;

        #pragma unroll
        for (int ks = 0; ks < 8; ks++) {
            const int C0 = 2 * ks, C1 = 2 * ks + 1;
            const int o0 = ((C0 & ~7) << 2) + off3[C0 & 7];
            const int o1 = ((C1 & ~7) << 2) + off3[C1 & 7];
            uint32_t a[2][4];
            #pragma unroll
            for (int mi = 0; mi < 2; mi++) {
                a[mi][0] = Hs[arH[mi][0] + o0];
                a[mi][1] = Hs[arH[mi][1] + o0];
                a[mi][2] = Hs[arH[mi][0] + o1];
                a[mi][3] = Hs[arH[mi][1] + o1];
            }
            #pragma unroll
            for (int ni = 0; ni < 4; ni++)
                #pragma unroll
                for (int mi = 0; mi < 2; mi++)
                    mma16(c2[mi][ni], a[mi][0], a[mi][1], a[mi][2], a[mi][3],
                          W2s[br2[ni] + o0], W2s[br2[ni] + o1]);
        }

        // ---- epilogue 2: + b2, atomic scatter ----
        #pragma unroll
        for (int mi = 0; mi < 2; mi++) {
            const int r0 = m0 + mi * 16 + g;
            const int ge0 = base + r0, ge1 = ge0 + 8;
            const int d0 = (ge0 < E) ? idxOut[ge0] : -1;
            const int d1 = (ge1 < E) ? idxOut[ge1] : -1;
            #pragma unroll
            for (int ni = 0; ni < 4; ni++) {
                const int col = nb + ni * 8 + 2 * t;
                const float2 bb = *(const float2*)(sB2 + col);
                if (d0 >= 0) {
                    float* p = accum + (size_t)d0 * HD + col;
                    atomicAdd(p,     c2[mi][ni][0] + bb.x);
                    atomicAdd(p + 1, c2[mi][ni][1] + bb.y);
                }
                if (d1 >= 0) {
                    float* p = accum + (size_t)d1 * HD + col;
                    atomicAdd(p,     c2[mi][ni][2] + bb.x);
                    atomicAdd(p + 1, c2[mi][ni][3] + bb.y);
                }
            }
        }
        // Xs stores of next tile happen after barrier (2); safe.
    }
}

// ---------------------------------------------------------------------------
// Node MLP: x = [self[i] | msum[i]*scale] (128) -> relu(x@W1+b1) (64)
//           -> @W2+b2 (64) -> direct store. 2 CTAs/SM.  (unchanged, proven)
// ---------------------------------------------------------------------------
__global__ void __launch_bounds__(NTPB, 2) node_mlp_tc(
    const float* __restrict__ selfF, const float* __restrict__ msum,
    const float* __restrict__ deg, const int* __restrict__ Sp,
    const float* __restrict__ W1, const float* __restrict__ b1,
    const float* __restrict__ W2, const float* __restrict__ b2,
    float* __restrict__ out, int N)
{
    extern __shared__ uint32_t smu[];
    uint32_t* W1s = smu + NW1_OFF;
    uint32_t* W2s = smu + NW2_OFF;
    uint32_t* Xs  = smu + NX_OFF;
    uint32_t* Hs  = smu + NH_OFF;
    float* sB1 = (float*)(smu + NB1_OFF);
    float* sB2 = (float*)(smu + NB2_OFF);

    const int tid = threadIdx.x;
    const int warp = tid >> 5, lane = tid & 31;
    const int g = lane >> 2, t = lane & 3;

    for (int i = tid; i < 64 * 64; i += NTPB) {
        const int kp = i >> 6, n = i & 63;
        const int ch = kp >> 2;
        const int cc = (ch & ~7) | ((ch & 7) ^ (n & 7));
        W1s[n * 64 + cc * 4 + (kp & 3)] =
            p2h(W1[(2 * kp) * 64 + n], W1[(2 * kp + 1) * 64 + n]);
    }
    for (int i = tid; i < 32 * 64; i += NTPB) {
        const int kp = i >> 6, n = i & 63;
        const int ch = kp >> 2;
        const int cc = (ch & ~7) | ((ch & 7) ^ (n & 7));
        W2s[n * 32 + cc * 4 + (kp & 3)] =
            p2h(W2[(2 * kp) * 64 + n], W2[(2 * kp + 1) * 64 + n]);
    }
    if (tid < 64) { sB1[tid] = b1[tid]; sB2[tid] = b2[tid]; }
    __syncthreads();

    const float invS = (Sp != nullptr) ? (1.0f / (float)(*Sp)) : 0.0f;

    int off3[8];
    #pragma unroll
    for (int c = 0; c < 8; c++) off3[c] = ((c ^ g) << 2) + t;

    const int m0 = (warp >> 1) * 32;
    const int n0 = (warp & 1) * 32;

    int arX[2][2], arH[2][2], brB[4], br2[4];
    #pragma unroll
    for (int mi = 0; mi < 2; mi++) {
        arX[mi][0] = (m0 + mi * 16 + g) * 64;
        arX[mi][1] = (m0 + mi * 16 + g + 8) * 64;
        arH[mi][0] = (m0 + mi * 16 + g) * 32;
        arH[mi][1] = (m0 + mi * 16 + g + 8) * 32;
    }
    #pragma unroll
    for (int ni = 0; ni < 4; ni++) {
        brB[ni] = (n0 + ni * 8 + g) * 64;
        br2[ni] = (n0 + ni * 8 + g) * 32;
    }

    const int sr = tid >> 1, half = tid & 1;
    const int ntiles = (N + 127) >> 7;

    for (int tile = blockIdx.x; tile < ntiles; tile += gridDim.x) {
        const int base = tile << 7;
        {
            const int i = base + sr;
            if (i < N) {
                if (half == 0) {
                    const float4* s = (const float4*)(selfF + (size_t)i * HD);
                    #pragma unroll
                    for (int j = 0; j < 8; j++)
                        st_chunk(Xs, sr, 64, j, pack8(s[2 * j], s[2 * j + 1]));
                } else {
                    const float sc = (Sp != nullptr) ? invS
                                                     : (1.0f / fmaxf(deg[i], 1.0f));
                    const float4* m = (const float4*)(msum + (size_t)i * HD);
                    #pragma unroll
                    for (int j = 0; j < 8; j++) {
                        float4 v0 = m[2 * j], v1 = m[2 * j + 1];
                        v0.x *= sc; v0.y *= sc; v0.z *= sc; v0.w *= sc;
                        v1.x *= sc; v1.y *= sc; v1.z *= sc; v1.w *= sc;
                        st_chunk(Xs, sr, 64, 8 + j, pack8(v0, v1));
                    }
                }
            }
        }
        __syncthreads();

        float c1[2][4][4];
        #pragma unroll
        for (int mi = 0; mi < 2; mi++)
            #pragma unroll
            for (int ni = 0; ni < 4; ni++)
                #pragma unroll
                for (int p = 0; p < 4; p++) c1[mi][ni][p] = 0.0f;

        #pragma unroll
        for (int ks = 0; ks < 8; ks++) {
            const int C0 = 2 * ks, C1 = 2 * ks + 1;
            const int o0 = ((C0 & ~7) << 2) + off3[C0 & 7];
            const int o1 = ((C1 & ~7) << 2) + off3[C1 & 7];
            uint32_t a[2][4];
            #pragma unroll
            for (int mi = 0; mi < 2; mi++) {
                a[mi][0] = Xs[arX[mi][0] + o0];
                a[mi][1] = Xs[arX[mi][1] + o0];
                a[mi][2] = Xs[arX[mi][0] + o1];
                a[mi][3] = Xs[arX[mi][1] + o1];
            }
            uint32_t b[4][2];
            #pragma unroll
            for (int ni = 0; ni < 4; ni++) {
                b[ni][0] = W1s[brB[ni] + o0];
                b[ni][1] = W1s[brB[ni] + o1];
            }
            #pragma unroll
            for (int mi = 0; mi < 2; mi++)
                #pragma unroll
                for (int ni = 0; ni < 4; ni++)
                    mma16(c1[mi][ni], a[mi][0], a[mi][1], a[mi][2], a[mi][3],
                          b[ni][0], b[ni][1]);
        }

        #pragma unroll
        for (int mi = 0; mi < 2; mi++) {
            const int r0 = m0 + mi * 16 + g;
            #pragma unroll
            for (int ni = 0; ni < 4; ni++) {
                const int col = n0 + ni * 8 + 2 * t;
                const float2 bb = *(const float2*)(sB1 + col);
                const int ch = (n0 >> 3) + ni;
                const int cc = (ch & ~7) | ((ch & 7) ^ g);
                const int wo = cc * 4 + t;
                Hs[r0 * 32 + wo] =
                    p2h(fmaxf(c1[mi][ni][0] + bb.x, 0.0f),
                        fmaxf(c1[mi][ni][1] + bb.y, 0.0f));
                Hs[(r0 + 8) * 32 + wo] =
                    p2h(fmaxf(c1[mi][ni][2] + bb.x, 0.0f),
                        fmaxf(c1[mi][ni][3] + bb.y, 0.0f));
            }
        }
        __syncthreads();

        float c2[2][4][4];
        #pragma unroll
        for (int mi = 0; mi < 2; mi++)
            #pragma unroll
            for (int ni = 0; ni < 4; ni++)
                #pragma unroll
                for (int p = 0; p < 4; p++) c2[mi][ni][p] = 0.0f;

        #pragma unroll
        for (int ks = 0; ks < 4; ks++) {
            const int C0 = 2 * ks, C1 = 2 * ks + 1;
            const int o0 = ((C0 & ~7) << 2) + off3[C0 & 7];
            const int o1 = ((C1 & ~7) << 2) + off3[C1 & 7];
            uint32_t a[2][4];
            #pragma unroll
            for (int mi = 0; mi < 2; mi++) {
                a[mi][0] = Hs[arH[mi][0] + o0];
                a[mi][1] = Hs[arH[mi][1] + o0];
                a[mi][2] = Hs[arH[mi][0] + o1];
                a[mi][3] = Hs[arH[mi][1] + o1];
            }
            uint32_t b[4][2];
            #pragma unroll
            for (int ni = 0; ni < 4; ni++) {
                b[ni][0] = W2s[br2[ni] + o0];
                b[ni][1] = W2s[br2[ni] + o1];
            }
            #pragma unroll
            for (int mi = 0; mi < 2; mi++)
                #pragma unroll
                for (int ni = 0; ni < 4; ni++)
                    mma16(c2[mi][ni], a[mi][0], a[mi][1], a[mi][2], a[mi][3],
                          b[ni][0], b[ni][1]);
        }

        #pragma unroll
        for (int mi = 0; mi < 2; mi++) {
            const int r0 = m0 + mi * 16 + g;
            const int gi0 = base + r0, gi1 = gi0 + 8;
            #pragma unroll
            for (int ni = 0; ni < 4; ni++) {
                const int col = n0 + ni * 8 + 2 * t;
                const float2 bb = *(const float2*)(sB2 + col);
                if (gi0 < N)
                    *(float2*)(out + (size_t)gi0 * HD + col) =
                        make_float2(c2[mi][ni][0] + bb.x, c2[mi][ni][1] + bb.y);
                if (gi1 < N)
                    *(float2*)(out + (size_t)gi1 * HD + col) =
                        make_float2(c2[mi][ni][2] + bb.x, c2[mi][ni][3] + bb.y);
            }
        }
        __syncthreads();
    }
}

// ---------------------------------------------------------------------------
extern "C" void kernel_launch(void* const* d_in, const int* in_sizes, int n_in,
                              void* d_out, int out_size)
{
    const float* h_v    = (const float*)d_in[0];
    const float* h_u    = (const float*)d_in[1];
    const float* e_feat = (const float*)d_in[2];
    const int*   ei     = (const int*)d_in[3];
    const int*   Sp     = (const int*)d_in[4];
    const float* a2u_w1 = (const float*)d_in[5];
    const float* a2u_b1 = (const float*)d_in[6];
    const float* a2u_w2 = (const float*)d_in[7];
    const float* a2u_b2 = (const float*)d_in[8];
    const float* u_w1   = (const float*)d_in[9];
    const float* u_b1   = (const float*)d_in[10];
    const float* u_w2   = (const float*)d_in[11];
    const float* u_b2   = (const float*)d_in[12];
    const float* u2a_w1 = (const float*)d_in[13];
    const float* u2a_b1 = (const float*)d_in[14];
    const float* u2a_w2 = (const float*)d_in[15];
    const float* u2a_b2 = (const float*)d_in[16];
    const float* a_w1   = (const float*)d_in[17];
    const float* a_b1   = (const float*)d_in[18];
    const float* a_w2   = (const float*)d_in[19];
    const float* a_b2   = (const float*)d_in[20];

    const int NVn = in_sizes[0] / HD;
    const int NUn = in_sizes[1] / HD;
    const int E   = in_sizes[3] / 2;
    const int* src = ei;
    const int* dst = ei + E;

    float *m_u = nullptr, *m_v = nullptr, *degp = nullptr;
    uint32_t *pA = nullptr, *pB = nullptr;
    cudaGetSymbolAddress((void**)&m_u, g_m_u);
    cudaGetSymbolAddress((void**)&m_v, g_m_v);
    cudaGetSymbolAddress((void**)&degp, g_deg);
    cudaGetSymbolAddress((void**)&pA, g_PA);
    cudaGetSymbolAddress((void**)&pB, g_PB);

    int sms = 148;
    cudaDeviceGetAttribute(&sms, cudaDevAttrMultiProcessorCount, 0);

    cudaFuncSetAttribute(edge_mlp_tc,
                         cudaFuncAttributeMaxDynamicSharedMemorySize, EDGE_SMEM);
    cudaFuncSetAttribute(node_mlp_tc,
                         cudaFuncAttributeMaxDynamicSharedMemorySize, NODE_SMEM);
    cudaFuncSetAttribute(pre_mlp,
                         cudaFuncAttributeMaxDynamicSharedMemorySize, PRE_SMEM);

    cudaMemsetAsync(m_u,  0, (size_t)NUn * HD * sizeof(float));
    cudaMemsetAsync(m_v,  0, (size_t)NVn * HD * sizeof(float));
    cudaMemsetAsync(degp, 0, (size_t)NVn * sizeof(float));

    float* h_v_out = (float*)d_out;
    float* h_u_out = (float*)d_out + (size_t)NVn * HD;

    const int etiles = (E + 127) >> 7;
    const int egrid = etiles < sms ? etiles : sms;
    const int vt = (NVn + 127) >> 7, ut = (NUn + 127) >> 7;
    const int pg_v = vt < 2 * sms ? vt : 2 * sms;
    const int pg_u = ut < 2 * sms ? ut : 2 * sms;

    // ---- pass 1: precompute + edge + node u ----
    pre_mlp<<<pg_v, PTPB, PRE_SMEM>>>(h_v, a2u_w1, a2u_b1, pA, NVn);
    pre_mlp<<<pg_u, PTPB, PRE_SMEM>>>(h_u, a2u_w1 + 64 * 128, nullptr, pB, NUn);

    edge_mlp_tc<<<egrid, ETPB, EDGE_SMEM>>>(
        pA, src, pB, dst, e_feat, dst,
        a2u_w1 + 128 * 128, a2u_w2, a2u_b2, m_u, degp, E);

    node_mlp_tc<<<pg_u, NTPB, NODE_SMEM>>>(
        h_u, m_u, nullptr, Sp,
        u_w1, u_b1, u_w2, u_b2, h_u_out, NUn);

    // ---- pass 2: precompute + edge + node v ----
    pre_mlp<<<pg_u, PTPB, PRE_SMEM>>>(h_u_out, u2a_w1, u2a_b1, pA, NUn);
    pre_mlp<<<pg_v, PTPB, PRE_SMEM>>>(h_v, u2a_w1 + 64 * 128, nullptr, pB, NVn);

    edge_mlp_tc<<<egrid, ETPB, EDGE_SMEM>>>(
        pA, dst, pB, src, e_feat, src,
        u2a_w1 + 128 * 128, u2a_w2, u2a_b2, m_v, nullptr, E);

    node_mlp_tc<<<pg_v, NTPB, NODE_SMEM>>>(
        h_v, m_v, degp, nullptr,
        a_w1, a_b1, a_w2, a_b2, h_v_out, NVn);
}

// round 14
// speedup vs baseline: 1.1773x; 1.1773x over previous
#include <cuda_runtime.h>
#include <cuda_fp16.h>
#include <cstdint>

// ---------------------------------------------------------------------------
// SparseMPNNLayer — factorized edge MLP on mma.sync m16n8k16 fp16, 2 CTAs/SM.
//   [A[src]|B[dst]|ef] @ W1 = (A@W1a+b1)[src] + (B@W1b)[dst] + ef@W1c
//   Node-level parts precomputed once (fused pre kernel, fp16 tables);
//   per-edge GEMM1 runs with K=64. Edge tile = 64 edges, 57.6KB smem,
//   2 CTAs/SM so gathers/epilogues overlap the other CTA's mma.
// ---------------------------------------------------------------------------

#define NTPB 256
#define ETPB 256
#define PTPB 256
constexpr int HD = 64;
constexpr int MAXN = 100000;

__device__ float    g_m_u[(size_t)MAXN * HD];
__device__ float    g_m_v[(size_t)MAXN * HD];
__device__ float    g_deg[MAXN];
__device__ uint32_t g_PA[(size_t)MAXN * 64];   // [N][128 halves] = 64 words
__device__ uint32_t g_PB[(size_t)MAXN * 64];

// ---- edge smem layout (words) ---------------------------------------------
constexpr int EW1_OFF = 0;                     // W1c  [128 n][64 k]h  (4096 w)
constexpr int EW2_OFF = EW1_OFF + 128 * 32;    // W2   [64 n][128 k]h  (4096 w)
constexpr int EX_OFF  = EW2_OFF + 64 * 64;     // ef   [64 e][64 k]h   (2048 w)
constexpr int EH_OFF  = EX_OFF + 64 * 32;      // H    [64 e][128 h]h  (4096 w)
constexpr int EB2_OFF = EH_OFF + 64 * 64;      // 64 f32
constexpr int EDGE_SMEM = (EB2_OFF + 64) * 4;  // 57856 B (x2 CTA = 115.7KB)

// ---- node smem layout (words) ---------------------------------------------
constexpr int NW1_OFF = 0;                     // [64 n][128 k]h
constexpr int NW2_OFF = NW1_OFF + 64 * 64;     // [64 n][64 k]h
constexpr int NX_OFF  = NW2_OFF + 64 * 32;     // [128 r][128 k]h
constexpr int NH_OFF  = NX_OFF + 128 * 64;     // [128 r][64 h]h
constexpr int NB1_OFF = NH_OFF + 128 * 32;     // 64 f32
constexpr int NB2_OFF = NB1_OFF + 64;          // 64 f32
constexpr int NODE_SMEM = (NB2_OFF + 64) * 4;  // 74240 B

// ---- pre smem layout (words) ----------------------------------------------
constexpr int PW_OFF  = 0;                     // [128 n][64 k]h (4096 w)
constexpr int PX_OFF  = PW_OFF + 128 * 32;     // [128 r][64 k]h (4096 w)
constexpr int PB_OFF  = PX_OFF + 128 * 32;     // 128 f32
constexpr int PRE_SMEM = (PB_OFF + 128) * 4;   // 33280 B

__device__ __forceinline__ uint32_t p2h(float a, float b) {
    __half2 h = __floats2half2_rn(a, b);   // low = a
    return *(uint32_t*)&h;
}
__device__ __forceinline__ uint4 pack8(float4 a, float4 b) {
    uint4 r;
    r.x = p2h(a.x, a.y); r.y = p2h(a.z, a.w);
    r.z = p2h(b.x, b.y); r.w = p2h(b.z, b.w);
    return r;
}

__device__ __forceinline__ void mma16(float* c, uint32_t a0, uint32_t a1,
                                      uint32_t a2, uint32_t a3,
                                      uint32_t b0, uint32_t b1) {
    asm("mma.sync.aligned.m16n8k16.row.col.f32.f16.f16.f32 "
        "{%0,%1,%2,%3}, {%4,%5,%6,%7}, {%8,%9}, {%0,%1,%2,%3};"
        : "+f"(c[0]), "+f"(c[1]), "+f"(c[2]), "+f"(c[3])
        : "r"(a0), "r"(a1), "r"(a2), "r"(a3), "r"(b0), "r"(b1));
}

// XOR-swizzled 16B-chunk store: row stride in words, chunk = 16B unit index.
__device__ __forceinline__ void st_chunk(uint32_t* b, int row, int stride,
                                         int chunk, uint4 v) {
    const int c = (chunk & ~7) | ((chunk & 7) ^ (row & 7));
    *(uint4*)(b + row * stride + c * 4) = v;
}

// ---------------------------------------------------------------------------
// pre2: fused precompute of BOTH tables.
//   CTAs [0, gA)       : OUTA[i] = XA[i] @ WA (+biasA)   (fp16 halves)
//   CTAs [gA, gA+gB)   : OUTB[i] = XB[i] @ WB
// Tile = 128 rows, 8 warps, warp = 32r x 64c, K=64. 2 CTAs/SM.
// ---------------------------------------------------------------------------
__global__ void __launch_bounds__(PTPB, 2) pre2(
    const float* __restrict__ XA, const float* __restrict__ WA,
    const float* __restrict__ biasA, uint32_t* __restrict__ OUTA, int NA, int gA,
    const float* __restrict__ XB, const float* __restrict__ WB,
    uint32_t* __restrict__ OUTB, int NB)
{
    extern __shared__ uint32_t smu[];
    uint32_t* Ws = smu + PW_OFF;
    uint32_t* Xs = smu + PX_OFF;
    float* sB = (float*)(smu + PB_OFF);

    const bool isA = ((int)blockIdx.x < gA);
    const float* X = isA ? XA : XB;
    const float* W = isA ? WA : WB;
    const float* bias = isA ? biasA : nullptr;
    uint32_t* OUT = isA ? OUTA : OUTB;
    const int N = isA ? NA : NB;
    const int bid = isA ? blockIdx.x : (blockIdx.x - gA);
    const int gstride = isA ? gA : (gridDim.x - gA);

    const int tid = threadIdx.x;
    const int warp = tid >> 5, lane = tid & 31;
    const int g = lane >> 2, t = lane & 3;

    for (int i = tid; i < 32 * 128; i += PTPB) {
        const int kp = i >> 7, n = i & 127;
        const int ch = kp >> 2;
        const int cc = (ch & ~7) | ((ch & 7) ^ (n & 7));
        Ws[n * 32 + cc * 4 + (kp & 3)] =
            p2h(W[(2 * kp) * 128 + n], W[(2 * kp + 1) * 128 + n]);
    }
    if (tid < 128) sB[tid] = (bias != nullptr) ? bias[tid] : 0.0f;
    __syncthreads();

    int off3[8];
    #pragma unroll
    for (int c = 0; c < 8; c++) off3[c] = ((c ^ g) << 2) + t;

    const int m0 = (warp >> 1) * 32;
    const int n0 = (warp & 1) * 64;

    int arX[2][2], brB[8];
    #pragma unroll
    for (int mi = 0; mi < 2; mi++) {
        arX[mi][0] = (m0 + mi * 16 + g) * 32;
        arX[mi][1] = (m0 + mi * 16 + g + 8) * 32;
    }
    #pragma unroll
    for (int ni = 0; ni < 8; ni++) brB[ni] = (n0 + ni * 8 + g) * 32;

    const int sr = tid >> 1, half = tid & 1;
    const int ntiles = (N + 127) >> 7;

    for (int tile = bid; tile < ntiles; tile += gstride) {
        const int base = tile << 7;
        {
            const int i = base + sr;
            if (i < N) {
                const float4* s = (const float4*)(X + (size_t)i * HD);
                #pragma unroll
                for (int j = 0; j < 4; j++) {
                    const int c = half * 4 + j;
                    st_chunk(Xs, sr, 32, c, pack8(s[2 * c], s[2 * c + 1]));
                }
            }
        }
        __syncthreads();

        float c1[2][8][4];
        #pragma unroll
        for (int mi = 0; mi < 2; mi++)
            #pragma unroll
            for (int ni = 0; ni < 8; ni++)
                #pragma unroll
                for (int p = 0; p < 4; p++) c1[mi][ni][p] = 0.0f;

        #pragma unroll
        for (int ks = 0; ks < 4; ks++) {
            const int C0 = 2 * ks, C1 = 2 * ks + 1;
            const int o0 = ((C0 & ~7) << 2) + off3[C0 & 7];
            const int o1 = ((C1 & ~7) << 2) + off3[C1 & 7];
            uint32_t a[2][4];
            #pragma unroll
            for (int mi = 0; mi < 2; mi++) {
                a[mi][0] = Xs[arX[mi][0] + o0];
                a[mi][1] = Xs[arX[mi][1] + o0];
                a[mi][2] = Xs[arX[mi][0] + o1];
                a[mi][3] = Xs[arX[mi][1] + o1];
            }
            #pragma unroll
            for (int ni = 0; ni < 8; ni++)
                #pragma unroll
                for (int mi = 0; mi < 2; mi++)
                    mma16(c1[mi][ni], a[mi][0], a[mi][1], a[mi][2], a[mi][3],
                          Ws[brB[ni] + o0], Ws[brB[ni] + o1]);
        }

        #pragma unroll
        for (int mi = 0; mi < 2; mi++) {
            const int gi0 = base + m0 + mi * 16 + g, gi1 = gi0 + 8;
            #pragma unroll
            for (int ni = 0; ni < 8; ni++) {
                const int col = n0 + ni * 8 + 2 * t;
                const float2 bb = *(const float2*)(sB + col);
                const int w = (col >> 1);
                if (gi0 < N)
                    OUT[(size_t)gi0 * 64 + w] =
                        p2h(c1[mi][ni][0] + bb.x, c1[mi][ni][1] + bb.y);
                if (gi1 < N)
                    OUT[(size_t)gi1 * 64 + w] =
                        p2h(c1[mi][ni][2] + bb.x, c1[mi][ni][3] + bb.y);
            }
        }
        __syncthreads();   // X reads done before next stage
    }
}

// ---------------------------------------------------------------------------
// Edge MLP (factorized, 2 CTAs/SM):
//   pre1 = PA[idxA[e]] + PB[idxB[e]] + ef@W1c     (PA carries +b1)
//   msg  = relu(pre1) @ W2 + b2 -> atomicAdd accum[idxOut[e]]
// Tile = 64 edges, 8 warps. GEMM1 warp: 16e x 64h (K=64).
// GEMM2 warp: 16e x 32o (K=128).
// ---------------------------------------------------------------------------
__global__ void __launch_bounds__(ETPB, 2) edge_mlp_tc(
    const uint32_t* __restrict__ PA, const int* __restrict__ idxA,
    const uint32_t* __restrict__ PB, const int* __restrict__ idxB,
    const float* __restrict__ EF, const int* __restrict__ idxOut,
    const float* __restrict__ W1c, const float* __restrict__ W2,
    const float* __restrict__ b2,
    float* __restrict__ accum, float* __restrict__ deg, int E)
{
    extern __shared__ uint32_t smu[];
    uint32_t* W1s = smu + EW1_OFF;
    uint32_t* W2s = smu + EW2_OFF;
    uint32_t* Xs  = smu + EX_OFF;
    uint32_t* Hs  = smu + EH_OFF;
    float* sB2 = (float*)(smu + EB2_OFF);

    const int tid = threadIdx.x;
    const int warp = tid >> 5, lane = tid & 31;
    const int g = lane >> 2, t = lane & 3;

    // ---- one-time: weights -> [n][k] halves, swizzled ---------------------
    for (int i = tid; i < 32 * 128; i += ETPB) {
        const int kp = i >> 7, n = i & 127;
        const int ch = kp >> 2;
        const int cc = (ch & ~7) | ((ch & 7) ^ (n & 7));
        W1s[n * 32 + cc * 4 + (kp & 3)] =
            p2h(W1c[(2 * kp) * 128 + n], W1c[(2 * kp + 1) * 128 + n]);
    }
    for (int i = tid; i < 64 * 64; i += ETPB) {
        const int kp = i >> 6, n = i & 63;
        const int ch = kp >> 2;
        const int cc = (ch & ~7) | ((ch & 7) ^ (n & 7));
        W2s[n * 64 + cc * 4 + (kp & 3)] =
            p2h(W2[(2 * kp) * 64 + n], W2[(2 * kp + 1) * 64 + n]);
    }
    if (tid < 64) sB2[tid] = b2[tid];

    int off3[8];
    #pragma unroll
    for (int c = 0; c < 8; c++) off3[c] = ((c ^ g) << 2) + t;

    const int m0 = (warp >> 1) * 16;       // 16 edge rows per warp pair
    const int n0 = (warp & 1) * 64;        // GEMM1 cols
    const int nb = (warp & 1) * 32;        // GEMM2 cols

    const int arA0 = (m0 + g) * 32, arA1 = (m0 + g + 8) * 32;
    const int arH0 = (m0 + g) * 64, arH1 = (m0 + g + 8) * 64;
    int brB[8], br2[4];
    #pragma unroll
    for (int ni = 0; ni < 8; ni++) brB[ni] = (n0 + ni * 8 + g) * 32;
    #pragma unroll
    for (int ni = 0; ni < 4; ni++) br2[ni] = (nb + ni * 8 + g) * 64;

    const int el = tid >> 2, q = tid & 3;  // staging: 64 edges x 4 threads
    const int ntiles = (E + 63) >> 6;

    for (int tile = blockIdx.x; tile < ntiles; tile += gridDim.x) {
        const int base = tile << 6;

        // ---- fragment gather: PA[idxA]+PB[idxB] as half2 (hidden) ---------
        uint32_t gth[2][8];
        #pragma unroll
        for (int r = 0; r < 2; r++) {
            const int ge = base + m0 + r * 8 + g;
            if (ge < E) {
                const uint32_t* pa = PA + (size_t)idxA[ge] * 64 + (n0 >> 1) + t;
                const uint32_t* pb = PB + (size_t)idxB[ge] * 64 + (n0 >> 1) + t;
                #pragma unroll
                for (int ni = 0; ni < 8; ni++) {
                    __half2 s = __hadd2(*(const __half2*)(pa + ni * 4),
                                        *(const __half2*)(pb + ni * 4));
                    gth[r][ni] = *(uint32_t*)&s;
                }
            } else {
                #pragma unroll
                for (int ni = 0; ni < 8; ni++) gth[r][ni] = 0;
            }
        }

        // ---- stage ef [64 rows][8 chunks], coalesced ----------------------
        {
            const int ge = base + el;
            if (ge < E) {
                const float4* s = (const float4*)(EF + (size_t)ge * HD);
                #pragma unroll
                for (int j = 0; j < 2; j++) {
                    const int c = q * 2 + j;
                    st_chunk(Xs, el, 32, c, pack8(s[2 * c], s[2 * c + 1]));
                }
            }
        }
        __syncthreads();   // (1) Xs ready (also covers weight staging)

        // ---- GEMM1': 16e x 64h, K=64 (4 k16 steps) ----
        float c1[8][4];
        #pragma unroll
        for (int ni = 0; ni < 8; ni++)
            #pragma unroll
            for (int p = 0; p < 4; p++) c1[ni][p] = 0.0f;

        #pragma unroll
        for (int ks = 0; ks < 4; ks++) {
            const int C0 = 2 * ks, C1 = 2 * ks + 1;
            const int o0 = ((C0 & ~7) << 2) + off3[C0 & 7];
            const int o1 = ((C1 & ~7) << 2) + off3[C1 & 7];
            const uint32_t a0 = Xs[arA0 + o0], a1 = Xs[arA1 + o0];
            const uint32_t a2 = Xs[arA0 + o1], a3 = Xs[arA1 + o1];
            #pragma unroll
            for (int ni = 0; ni < 8; ni++)
                mma16(c1[ni], a0, a1, a2, a3,
                      W1s[brB[ni] + o0], W1s[brB[ni] + o1]);
        }

        // ---- epilogue 1: relu(c1 + gathered) -> H (fp16, swizzled) ----
        {
            const int r0 = m0 + g;
            #pragma unroll
            for (int ni = 0; ni < 8; ni++) {
                const __half2 g0 = *(__half2*)&gth[0][ni];
                const __half2 g1 = *(__half2*)&gth[1][ni];
                const int ch = (n0 >> 3) + ni;
                const int cc = (ch & ~7) | ((ch & 7) ^ g);
                const int wo = cc * 4 + t;
                Hs[r0 * 64 + wo] =
                    p2h(fmaxf(c1[ni][0] + __low2float(g0), 0.0f),
                        fmaxf(c1[ni][1] + __high2float(g0), 0.0f));
                Hs[(r0 + 8) * 64 + wo] =
                    p2h(fmaxf(c1[ni][2] + __low2float(g1), 0.0f),
                        fmaxf(c1[ni][3] + __high2float(g1), 0.0f));
            }
        }
        if (deg != nullptr && tid < 64) {
            const int ge = base + tid;
            if (ge < E) atomicAdd(deg + idxA[ge], 1.0f);
        }
        __syncthreads();   // (2) H ready (Xs reads done)

        // ---- GEMM2: 16e x 32o, K=128 (8 k16 steps) ----
        float c2[4][4];
        #pragma unroll
        for (int ni = 0; ni < 4; ni++)
            #pragma unroll
            for (int p = 0; p < 4; p++) c2[ni][p] = 0.0f;

        #pragma unroll
        for (int ks = 0; ks < 8; ks++) {
            const int C0 = 2 * ks, C1 = 2 * ks + 1;
            const int o0 = ((C0 & ~7) << 2) + off3[C0 & 7];
            const int o1 = ((C1 & ~7) << 2) + off3[C1 & 7];
            const uint32_t a0 = Hs[arH0 + o0], a1 = Hs[arH1 + o0];
            const uint32_t a2 = Hs[arH0 + o1], a3 = Hs[arH1 + o1];
            #pragma unroll
            for (int ni = 0; ni < 4; ni++)
                mma16(c2[ni], a0, a1, a2, a3,
                      W2s[br2[ni] + o0], W2s[br2[ni] + o1]);
        }

        // ---- epilogue 2: + b2, atomic scatter ----
        {
            const int ge0 = base + m0 + g, ge1 = ge0 + 8;
            const int d0 = (ge0 < E) ? idxOut[ge0] : -1;
            const int d1 = (ge1 < E) ? idxOut[ge1] : -1;
            #pragma unroll
            for (int ni = 0; ni < 4; ni++) {
                const int col = nb + ni * 8 + 2 * t;
                const float2 bb = *(const float2*)(sB2 + col);
                if (d0 >= 0) {
                    float* p = accum + (size_t)d0 * HD + col;
                    atomicAdd(p,     c2[ni][0] + bb.x);
                    atomicAdd(p + 1, c2[ni][1] + bb.y);
                }
                if (d1 >= 0) {
                    float* p = accum + (size_t)d1 * HD + col;
                    atomicAdd(p,     c2[ni][2] + bb.x);
                    atomicAdd(p + 1, c2[ni][3] + bb.y);
                }
            }
        }
        // next-tile Xs staging happens after this iteration's barrier (2);
        // H reads (GEMM2) complete before next epilogue-1 writes (ordered by
        // next iteration's barrier (1)).
    }
}

// ---------------------------------------------------------------------------
// Node MLP: x = [self[i] | msum[i]*scale] (128) -> relu(x@W1+b1) (64)
//           -> @W2+b2 (64) -> direct store. 2 CTAs/SM.  (unchanged, proven)
// ---------------------------------------------------------------------------
__global__ void __launch_bounds__(NTPB, 2) node_mlp_tc(
    const float* __restrict__ selfF, const float* __restrict__ msum,
    const float* __restrict__ deg, const int* __restrict__ Sp,
    const float* __restrict__ W1, const float* __restrict__ b1,
    const float* __restrict__ W2, const float* __restrict__ b2,
    float* __restrict__ out, int N)
{
    extern __shared__ uint32_t smu[];
    uint32_t* W1s = smu + NW1_OFF;
    uint32_t* W2s = smu + NW2_OFF;
    uint32_t* Xs  = smu + NX_OFF;
    uint32_t* Hs  = smu + NH_OFF;
    float* sB1 = (float*)(smu + NB1_OFF);
    float* sB2 = (float*)(smu + NB2_OFF);

    const int tid = threadIdx.x;
    const int warp = tid >> 5, lane = tid & 31;
    const int g = lane >> 2, t = lane & 3;

    for (int i = tid; i < 64 * 64; i += NTPB) {
        const int kp = i >> 6, n = i & 63;
        const int ch = kp >> 2;
        const int cc = (ch & ~7) | ((ch & 7) ^ (n & 7));
        W1s[n * 64 + cc * 4 + (kp & 3)] =
            p2h(W1[(2 * kp) * 64 + n], W1[(2 * kp + 1) * 64 + n]);
    }
    for (int i = tid; i < 32 * 64; i += NTPB) {
        const int kp = i >> 6, n = i & 63;
        const int ch = kp >> 2;
        const int cc = (ch & ~7) | ((ch & 7) ^ (n & 7));
        W2s[n * 32 + cc * 4 + (kp & 3)] =
            p2h(W2[(2 * kp) * 64 + n], W2[(2 * kp + 1) * 64 + n]);
    }
    if (tid < 64) { sB1[tid] = b1[tid]; sB2[tid] = b2[tid]; }
    __syncthreads();

    const float invS = (Sp != nullptr) ? (1.0f / (float)(*Sp)) : 0.0f;

    int off3[8];
    #pragma unroll
    for (int c = 0; c < 8; c++) off3[c] = ((c ^ g) << 2) + t;

    const int m0 = (warp >> 1) * 32;
    const int n0 = (warp & 1) * 32;

    int arX[2][2], arH[2][2], brB[4], br2[4];
    #pragma unroll
    for (int mi = 0; mi < 2; mi++) {
        arX[mi][0] = (m0 + mi * 16 + g) * 64;
        arX[mi][1] = (m0 + mi * 16 + g + 8) * 64;
        arH[mi][0] = (m0 + mi * 16 + g) * 32;
        arH[mi][1] = (m0 + mi * 16 + g + 8) * 32;
    }
    #pragma unroll
    for (int ni = 0; ni < 4; ni++) {
        brB[ni] = (n0 + ni * 8 + g) * 64;
        br2[ni] = (n0 + ni * 8 + g) * 32;
    }

    const int sr = tid >> 1, half = tid & 1;
    const int ntiles = (N + 127) >> 7;

    for (int tile = blockIdx.x; tile < ntiles; tile += gridDim.x) {
        const int base = tile << 7;
        {
            const int i = base + sr;
            if (i < N) {
                if (half == 0) {
                    const float4* s = (const float4*)(selfF + (size_t)i * HD);
                    #pragma unroll
                    for (int j = 0; j < 8; j++)
                        st_chunk(Xs, sr, 64, j, pack8(s[2 * j], s[2 * j + 1]));
                } else {
                    const float sc = (Sp != nullptr) ? invS
                                                     : (1.0f / fmaxf(deg[i], 1.0f));
                    const float4* m = (const float4*)(msum + (size_t)i * HD);
                    #pragma unroll
                    for (int j = 0; j < 8; j++) {
                        float4 v0 = m[2 * j], v1 = m[2 * j + 1];
                        v0.x *= sc; v0.y *= sc; v0.z *= sc; v0.w *= sc;
                        v1.x *= sc; v1.y *= sc; v1.z *= sc; v1.w *= sc;
                        st_chunk(Xs, sr, 64, 8 + j, pack8(v0, v1));
                    }
                }
            }
        }
        __syncthreads();

        float c1[2][4][4];
        #pragma unroll
        for (int mi = 0; mi < 2; mi++)
            #pragma unroll
            for (int ni = 0; ni < 4; ni++)
                #pragma unroll
                for (int p = 0; p < 4; p++) c1[mi][ni][p] = 0.0f;

        #pragma unroll
        for (int ks = 0; ks < 8; ks++) {
            const int C0 = 2 * ks, C1 = 2 * ks + 1;
            const int o0 = ((C0 & ~7) << 2) + off3[C0 & 7];
            const int o1 = ((C1 & ~7) << 2) + off3[C1 & 7];
            uint32_t a[2][4];
            #pragma unroll
            for (int mi = 0; mi < 2; mi++) {
                a[mi][0] = Xs[arX[mi][0] + o0];
                a[mi][1] = Xs[arX[mi][1] + o0];
                a[mi][2] = Xs[arX[mi][0] + o1];
                a[mi][3] = Xs[arX[mi][1] + o1];
            }
            uint32_t b[4][2];
            #pragma unroll
            for (int ni = 0; ni < 4; ni++) {
                b[ni][0] = W1s[brB[ni] + o0];
                b[ni][1] = W1s[brB[ni] + o1];
            }
            #pragma unroll
            for (int mi = 0; mi < 2; mi++)
                #pragma unroll
                for (int ni = 0; ni < 4; ni++)
                    mma16(c1[mi][ni], a[mi][0], a[mi][1], a[mi][2], a[mi][3],
                          b[ni][0], b[ni][1]);
        }

        #pragma unroll
        for (int mi = 0; mi < 2; mi++) {
            const int r0 = m0 + mi * 16 + g;
            #pragma unroll
            for (int ni = 0; ni < 4; ni++) {
                const int col = n0 + ni * 8 + 2 * t;
                const float2 bb = *(const float2*)(sB1 + col);
                const int ch = (n0 >> 3) + ni;
                const int cc = (ch & ~7) | ((ch & 7) ^ g);
                const int wo = cc * 4 + t;
                Hs[r0 * 32 + wo] =
                    p2h(fmaxf(c1[mi][ni][0] + bb.x, 0.0f),
                        fmaxf(c1[mi][ni][1] + bb.y, 0.0f));
                Hs[(r0 + 8) * 32 + wo] =
                    p2h(fmaxf(c1[mi][ni][2] + bb.x, 0.0f),
                        fmaxf(c1[mi][ni][3] + bb.y, 0.0f));
            }
        }
        __syncthreads();

        float c2[2][4][4];
        #pragma unroll
        for (int mi = 0; mi < 2; mi++)
            #pragma unroll
            for (int ni = 0; ni < 4; ni++)
                #pragma unroll
                for (int p = 0; p < 4; p++) c2[mi][ni][p] = 0.0f;

        #pragma unroll
        for (int ks = 0; ks < 4; ks++) {
            const int C0 = 2 * ks, C1 = 2 * ks + 1;
            const int o0 = ((C0 & ~7) << 2) + off3[C0 & 7];
            const int o1 = ((C1 & ~7) << 2) + off3[C1 & 7];
            uint32_t a[2][4];
            #pragma unroll
            for (int mi = 0; mi < 2; mi++) {
                a[mi][0] = Hs[arH[mi][0] + o0];
                a[mi][1] = Hs[arH[mi][1] + o0];
                a[mi][2] = Hs[arH[mi][0] + o1];
                a[mi][3] = Hs[arH[mi][1] + o1];
            }
            uint32_t b[4][2];
            #pragma unroll
            for (int ni = 0; ni < 4; ni++) {
                b[ni][0] = W2s[br2[ni] + o0];
                b[ni][1] = W2s[br2[ni] + o1];
            }
            #pragma unroll
            for (int mi = 0; mi < 2; mi++)
                #pragma unroll
                for (int ni = 0; ni < 4; ni++)
                    mma16(c2[mi][ni], a[mi][0], a[mi][1], a[mi][2], a[mi][3],
                          b[ni][0], b[ni][1]);
        }

        #pragma unroll
        for (int mi = 0; mi < 2; mi++) {
            const int r0 = m0 + mi * 16 + g;
            const int gi0 = base + r0, gi1 = gi0 + 8;
            #pragma unroll
            for (int ni = 0; ni < 4; ni++) {
                const int col = n0 + ni * 8 + 2 * t;
                const float2 bb = *(const float2*)(sB2 + col);
                if (gi0 < N)
                    *(float2*)(out + (size_t)gi0 * HD + col) =
                        make_float2(c2[mi][ni][0] + bb.x, c2[mi][ni][1] + bb.y);
                if (gi1 < N)
                    *(float2*)(out + (size_t)gi1 * HD + col) =
                        make_float2(c2[mi][ni][2] + bb.x, c2[mi][ni][3] + bb.y);
            }
        }
        __syncthreads();
    }
}

// ---------------------------------------------------------------------------
extern "C" void kernel_launch(void* const* d_in, const int* in_sizes, int n_in,
                              void* d_out, int out_size)
{
    const float* h_v    = (const float*)d_in[0];
    const float* h_u    = (const float*)d_in[1];
    const float* e_feat = (const float*)d_in[2];
    const int*   ei     = (const int*)d_in[3];
    const int*   Sp     = (const int*)d_in[4];
    const float* a2u_w1 = (const float*)d_in[5];
    const float* a2u_b1 = (const float*)d_in[6];
    const float* a2u_w2 = (const float*)d_in[7];
    const float* a2u_b2 = (const float*)d_in[8];
    const float* u_w1   = (const float*)d_in[9];
    const float* u_b1   = (const float*)d_in[10];
    const float* u_w2   = (const float*)d_in[11];
    const float* u_b2   = (const float*)d_in[12];
    const float* u2a_w1 = (const float*)d_in[13];
    const float* u2a_b1 = (const float*)d_in[14];
    const float* u2a_w2 = (const float*)d_in[15];
    const float* u2a_b2 = (const float*)d_in[16];
    const float* a_w1   = (const float*)d_in[17];
    const float* a_b1   = (const float*)d_in[18];
    const float* a_w2   = (const float*)d_in[19];
    const float* a_b2   = (const float*)d_in[20];

    const int NVn = in_sizes[0] / HD;
    const int NUn = in_sizes[1] / HD;
    const int E   = in_sizes[3] / 2;
    const int* src = ei;
    const int* dst = ei + E;

    float *m_u = nullptr, *m_v = nullptr, *degp = nullptr;
    uint32_t *pA = nullptr, *pB = nullptr;
    cudaGetSymbolAddress((void**)&m_u, g_m_u);
    cudaGetSymbolAddress((void**)&m_v, g_m_v);
    cudaGetSymbolAddress((void**)&degp, g_deg);
    cudaGetSymbolAddress((void**)&pA, g_PA);
    cudaGetSymbolAddress((void**)&pB, g_PB);

    int sms = 148;
    cudaDeviceGetAttribute(&sms, cudaDevAttrMultiProcessorCount, 0);

    cudaFuncSetAttribute(edge_mlp_tc,
                         cudaFuncAttributeMaxDynamicSharedMemorySize, EDGE_SMEM);
    cudaFuncSetAttribute(node_mlp_tc,
                         cudaFuncAttributeMaxDynamicSharedMemorySize, NODE_SMEM);
    cudaFuncSetAttribute(pre2,
                         cudaFuncAttributeMaxDynamicSharedMemorySize, PRE_SMEM);

    cudaMemsetAsync(m_u,  0, (size_t)NUn * HD * sizeof(float));
    cudaMemsetAsync(m_v,  0, (size_t)NVn * HD * sizeof(float));
    cudaMemsetAsync(degp, 0, (size_t)NVn * sizeof(float));

    float* h_v_out = (float*)d_out;
    float* h_u_out = (float*)d_out + (size_t)NVn * HD;

    const int etiles = (E + 63) >> 6;
    const int egrid = etiles < 2 * sms ? etiles : 2 * sms;
    const int vt = (NVn + 127) >> 7, ut = (NUn + 127) >> 7;
    const int gA1 = vt < sms ? vt : sms;      // pass1: A-table from h_v
    const int gB1 = ut < sms ? ut : sms;
    const int gA2 = ut < sms ? ut : sms;      // pass2: A-table from h_u_out
    const int gB2 = vt < sms ? vt : sms;
    const int pg_u = ut < 2 * sms ? ut : 2 * sms;
    const int pg_v = vt < 2 * sms ? vt : 2 * sms;

    // ---- pass 1: fused precompute + edge + node u ----
    pre2<<<gA1 + gB1, PTPB, PRE_SMEM>>>(
        h_v, a2u_w1, a2u_b1, pA, NVn, gA1,
        h_u, a2u_w1 + 64 * 128, pB, NUn);

    edge_mlp_tc<<<egrid, ETPB, EDGE_SMEM>>>(
        pA, src, pB, dst, e_feat, dst,
        a2u_w1 + 128 * 128, a2u_w2, a2u_b2, m_u, degp, E);

    node_mlp_tc<<<pg_u, NTPB, NODE_SMEM>>>(
        h_u, m_u, nullptr, Sp,
        u_w1, u_b1, u_w2, u_b2, h_u_out, NUn);

    // ---- pass 2: fused precompute + edge + node v ----
    pre2<<<gA2 + gB2, PTPB, PRE_SMEM>>>(
        h_u_out, u2a_w1, u2a_b1, pA, NUn, gA2,
        h_v, u2a_w1 + 64 * 128, pB, NVn);

    edge_mlp_tc<<<egrid, ETPB, EDGE_SMEM>>>(
        pA, dst, pB, src, e_feat, src,
        u2a_w1 + 128 * 128, u2a_w2, u2a_b2, m_v, nullptr, E);

    node_mlp_tc<<<pg_v, NTPB, NODE_SMEM>>>(
        h_v, m_v, degp, nullptr,
        a_w1, a_b1, a_w2, a_b2, h_v_out, NVn);
}

// round 16
// speedup vs baseline: 1.1913x; 1.0119x over previous
#include <cuda_runtime.h>
#include <cuda_fp16.h>
#include <cstdint>

// ---------------------------------------------------------------------------
// SparseMPNNLayer — factorized edge MLP, register-fused GEMM1->GEMM2.
//   [A[src]|B[dst]|ef] @ W1 = (A@W1a+b1)[src] + (B@W1b)[dst] + ef@W1c
//   Node-level parts precomputed (pre2, fp16 tables). Edge kernel computes
//   ef@W1c (K=64) into full-width accumulators, adds gathered tables, relus
//   in registers, and feeds GEMM2 A-fragments directly from registers:
//   no H smem, ONE barrier per tile, ef double-buffered + prefetched.
// ---------------------------------------------------------------------------

#define NTPB 256
#define ETPB 256
#define PTPB 256
constexpr int HD = 64;
constexpr int MAXN = 100000;

__device__ float    g_m_u[(size_t)MAXN * HD];
__device__ float    g_m_v[(size_t)MAXN * HD];
__device__ float    g_deg[MAXN];
__device__ uint32_t g_PA[(size_t)MAXN * 64];   // [N][128 halves] = 64 words
__device__ uint32_t g_PB[(size_t)MAXN * 64];

// ---- edge smem layout (words) ---------------------------------------------
constexpr int EW1_OFF = 0;                     // W1c [128 n][64 k]h (4096 w)
constexpr int EW2_OFF = EW1_OFF + 128 * 32;    // W2  [64 n][128 k]h (4096 w)
constexpr int EX0_OFF = EW2_OFF + 64 * 64;     // ef buf0 [128 e][64 k]h
constexpr int EX1_OFF = EX0_OFF + 128 * 32;    // ef buf1
constexpr int EB2_OFF = EX1_OFF + 128 * 32;    // 64 f32
constexpr int EDGE_SMEM = (EB2_OFF + 64) * 4;  // 66048 B

// ---- node smem layout (words) ---------------------------------------------
constexpr int NW1_OFF = 0;                     // [64 n][128 k]h
constexpr int NW2_OFF = NW1_OFF + 64 * 64;     // [64 n][64 k]h
constexpr int NX_OFF  = NW2_OFF + 64 * 32;     // [128 r][128 k]h
constexpr int NH_OFF  = NX_OFF + 128 * 64;     // [128 r][64 h]h
constexpr int NB1_OFF = NH_OFF + 128 * 32;     // 64 f32
constexpr int NB2_OFF = NB1_OFF + 64;          // 64 f32
constexpr int NODE_SMEM = (NB2_OFF + 64) * 4;  // 74240 B

// ---- pre smem layout (words) ----------------------------------------------
constexpr int PW_OFF  = 0;                     // [128 n][64 k]h (4096 w)
constexpr int PX_OFF  = PW_OFF + 128 * 32;     // [128 r][64 k]h (4096 w)
constexpr int PB_OFF  = PX_OFF + 128 * 32;     // 128 f32
constexpr int PRE_SMEM = (PB_OFF + 128) * 4;   // 33280 B

__device__ __forceinline__ uint32_t p2h(float a, float b) {
    __half2 h = __floats2half2_rn(a, b);   // low = a
    return *(uint32_t*)&h;
}
__device__ __forceinline__ uint4 pack8(float4 a, float4 b) {
    uint4 r;
    r.x = p2h(a.x, a.y); r.y = p2h(a.z, a.w);
    r.z = p2h(b.x, b.y); r.w = p2h(b.z, b.w);
    return r;
}

__device__ __forceinline__ void mma16(float* c, uint32_t a0, uint32_t a1,
                                      uint32_t a2, uint32_t a3,
                                      uint32_t b0, uint32_t b1) {
    asm("mma.sync.aligned.m16n8k16.row.col.f32.f16.f16.f32 "
        "{%0,%1,%2,%3}, {%4,%5,%6,%7}, {%8,%9}, {%0,%1,%2,%3};"
        : "+f"(c[0]), "+f"(c[1]), "+f"(c[2]), "+f"(c[3])
        : "r"(a0), "r"(a1), "r"(a2), "r"(a3), "r"(b0), "r"(b1));
}

// XOR-swizzled 16B-chunk store: row stride in words, chunk = 16B unit index.
__device__ __forceinline__ void st_chunk(uint32_t* b, int row, int stride,
                                         int chunk, uint4 v) {
    const int c = (chunk & ~7) | ((chunk & 7) ^ (row & 7));
    *(uint4*)(b + row * stride + c * 4) = v;
}

// Gather one edge's table row-sum into 16 fragment words (or zero).
__device__ __forceinline__ void gather_row(
    uint32_t* dstv, const uint32_t* __restrict__ PA,
    const uint32_t* __restrict__ PB, const int* __restrict__ idxA,
    const int* __restrict__ idxB, int ge, int E, int t)
{
    if (ge < E) {
        const uint32_t* pa = PA + (size_t)idxA[ge] * 64 + t;
        const uint32_t* pb = PB + (size_t)idxB[ge] * 64 + t;
        #pragma unroll
        for (int ni = 0; ni < 16; ni++) {
            __half2 s = __hadd2(*(const __half2*)(pa + ni * 4),
                                *(const __half2*)(pb + ni * 4));
            dstv[ni] = *(uint32_t*)&s;
        }
    } else {
        #pragma unroll
        for (int ni = 0; ni < 16; ni++) dstv[ni] = 0;
    }
}

// ---------------------------------------------------------------------------
// pre2: fused precompute of BOTH tables.
//   CTAs [0, gA)     : OUTA[i] = XA[i] @ WA (+biasA)
//   CTAs [gA, ...)   : OUTB[i] = XB[i] @ WB
// ---------------------------------------------------------------------------
__global__ void __launch_bounds__(PTPB, 2) pre2(
    const float* __restrict__ XA, const float* __restrict__ WA,
    const float* __restrict__ biasA, uint32_t* __restrict__ OUTA, int NA, int gA,
    const float* __restrict__ XB, const float* __restrict__ WB,
    uint32_t* __restrict__ OUTB, int NB)
{
    extern __shared__ uint32_t smu[];
    uint32_t* Ws = smu + PW_OFF;
    uint32_t* Xs = smu + PX_OFF;
    float* sB = (float*)(smu + PB_OFF);

    const bool isA = ((int)blockIdx.x < gA);
    const float* X = isA ? XA : XB;
    const float* W = isA ? WA : WB;
    const float* bias = isA ? biasA : nullptr;
    uint32_t* OUT = isA ? OUTA : OUTB;
    const int N = isA ? NA : NB;
    const int bid = isA ? blockIdx.x : (blockIdx.x - gA);
    const int gstride = isA ? gA : (gridDim.x - gA);

    const int tid = threadIdx.x;
    const int warp = tid >> 5, lane = tid & 31;
    const int g = lane >> 2, t = lane & 3;

    for (int i = tid; i < 32 * 128; i += PTPB) {
        const int kp = i >> 7, n = i & 127;
        const int ch = kp >> 2;
        const int cc = (ch & ~7) | ((ch & 7) ^ (n & 7));
        Ws[n * 32 + cc * 4 + (kp & 3)] =
            p2h(W[(2 * kp) * 128 + n], W[(2 * kp + 1) * 128 + n]);
    }
    if (tid < 128) sB[tid] = (bias != nullptr) ? bias[tid] : 0.0f;
    __syncthreads();

    int off3[8];
    #pragma unroll
    for (int c = 0; c < 8; c++) off3[c] = ((c ^ g) << 2) + t;

    const int m0 = (warp >> 1) * 32;
    const int n0 = (warp & 1) * 64;

    int arX[2][2], brB[8];
    #pragma unroll
    for (int mi = 0; mi < 2; mi++) {
        arX[mi][0] = (m0 + mi * 16 + g) * 32;
        arX[mi][1] = (m0 + mi * 16 + g + 8) * 32;
    }
    #pragma unroll
    for (int ni = 0; ni < 8; ni++) brB[ni] = (n0 + ni * 8 + g) * 32;

    const int sr = tid >> 1, half = tid & 1;
    const int ntiles = (N + 127) >> 7;

    for (int tile = bid; tile < ntiles; tile += gstride) {
        const int base = tile << 7;
        {
            const int i = base + sr;
            if (i < N) {
                const float4* s = (const float4*)(X + (size_t)i * HD);
                #pragma unroll
                for (int j = 0; j < 4; j++) {
                    const int c = half * 4 + j;
                    st_chunk(Xs, sr, 32, c, pack8(s[2 * c], s[2 * c + 1]));
                }
            }
        }
        __syncthreads();

        float c1[2][8][4];
        #pragma unroll
        for (int mi = 0; mi < 2; mi++)
            #pragma unroll
            for (int ni = 0; ni < 8; ni++)
                #pragma unroll
                for (int p = 0; p < 4; p++) c1[mi][ni][p] = 0.0f;

        #pragma unroll
        for (int ks = 0; ks < 4; ks++) {
            const int C0 = 2 * ks, C1 = 2 * ks + 1;
            const int o0 = ((C0 & ~7) << 2) + off3[C0 & 7];
            const int o1 = ((C1 & ~7) << 2) + off3[C1 & 7];
            uint32_t a[2][4];
            #pragma unroll
            for (int mi = 0; mi < 2; mi++) {
                a[mi][0] = Xs[arX[mi][0] + o0];
                a[mi][1] = Xs[arX[mi][1] + o0];
                a[mi][2] = Xs[arX[mi][0] + o1];
                a[mi][3] = Xs[arX[mi][1] + o1];
            }
            #pragma unroll
            for (int ni = 0; ni < 8; ni++)
                #pragma unroll
                for (int mi = 0; mi < 2; mi++)
                    mma16(c1[mi][ni], a[mi][0], a[mi][1], a[mi][2], a[mi][3],
                          Ws[brB[ni] + o0], Ws[brB[ni] + o1]);
        }

        #pragma unroll
        for (int mi = 0; mi < 2; mi++) {
            const int gi0 = base + m0 + mi * 16 + g, gi1 = gi0 + 8;
            #pragma unroll
            for (int ni = 0; ni < 8; ni++) {
                const int col = n0 + ni * 8 + 2 * t;
                const float2 bb = *(const float2*)(sB + col);
                const int w = (col >> 1);
                if (gi0 < N)
                    OUT[(size_t)gi0 * 64 + w] =
                        p2h(c1[mi][ni][0] + bb.x, c1[mi][ni][1] + bb.y);
                if (gi1 < N)
                    OUT[(size_t)gi1 * 64 + w] =
                        p2h(c1[mi][ni][2] + bb.x, c1[mi][ni][3] + bb.y);
            }
        }
        __syncthreads();
    }
}

// ---------------------------------------------------------------------------
// Edge MLP (factorized, register-fused):
//   warp = 16 edges x full 128 hidden. c1 = ef@W1c (K=64);
//   ah = relu(c1 + PA[idxA]+PB[idxB]) packed to fp16 in registers;
//   c2 = ah @ W2 (64 out), A-fragments straight from ah registers;
//   out: + b2, atomic scatter. Tile = 128 edges, ONE barrier/tile.
// ---------------------------------------------------------------------------
__global__ void __launch_bounds__(ETPB, 1) edge_mlp_tc(
    const uint32_t* __restrict__ PA, const int* __restrict__ idxA,
    const uint32_t* __restrict__ PB, const int* __restrict__ idxB,
    const float* __restrict__ EF, const int* __restrict__ idxOut,
    const float* __restrict__ W1c, const float* __restrict__ W2,
    const float* __restrict__ b2,
    float* __restrict__ accum, float* __restrict__ deg, int E)
{
    extern __shared__ uint32_t smu[];
    uint32_t* W1s = smu + EW1_OFF;
    uint32_t* W2s = smu + EW2_OFF;
    float* sB2 = (float*)(smu + EB2_OFF);

    const int tid = threadIdx.x;
    const int warp = tid >> 5, lane = tid & 31;
    const int g = lane >> 2, t = lane & 3;

    // ---- one-time: weights -> [n][k] halves, swizzled ---------------------
    for (int i = tid; i < 32 * 128; i += ETPB) {
        const int kp = i >> 7, n = i & 127;
        const int ch = kp >> 2;
        const int cc = (ch & ~7) | ((ch & 7) ^ (n & 7));
        W1s[n * 32 + cc * 4 + (kp & 3)] =
            p2h(W1c[(2 * kp) * 128 + n], W1c[(2 * kp + 1) * 128 + n]);
    }
    for (int i = tid; i < 64 * 64; i += ETPB) {
        const int kp = i >> 6, n = i & 63;
        const int ch = kp >> 2;
        const int cc = (ch & ~7) | ((ch & 7) ^ (n & 7));
        W2s[n * 64 + cc * 4 + (kp & 3)] =
            p2h(W2[(2 * kp) * 64 + n], W2[(2 * kp + 1) * 64 + n]);
    }
    if (tid < 64) sB2[tid] = b2[tid];

    int off3[8];
    #pragma unroll
    for (int c = 0; c < 8; c++) off3[c] = ((c ^ g) << 2) + t;

    const int m0 = warp * 16;                       // 16 edges per warp
    const int arA0 = (m0 + g) * 32, arA1 = (m0 + g + 8) * 32;
    int brB[16], br2[8];
    #pragma unroll
    for (int ni = 0; ni < 16; ni++) brB[ni] = (ni * 8 + g) * 32;
    #pragma unroll
    for (int ni = 0; ni < 8; ni++)  br2[ni] = (ni * 8 + g) * 64;

    const int sr = tid >> 1, half = tid & 1;        // ef staging roles
    const int ntiles = (E + 127) >> 7;

    uint32_t* Xc = smu + EX0_OFF;
    uint32_t* Xn = smu + EX1_OFF;

    int tile = blockIdx.x;

    // ---- prologue: stage ef(tile0) into Xc; load gth(tile0) ---------------
    if (tile < ntiles) {
        const int ge = (tile << 7) + sr;
        if (ge < E) {
            const float4* s = (const float4*)(EF + (size_t)ge * HD);
            #pragma unroll
            for (int j = 0; j < 4; j++) {
                const int c = half * 4 + j;
                st_chunk(Xc, sr, 32, c, pack8(s[2 * c], s[2 * c + 1]));
            }
        }
    }
    uint32_t gth0[16], gth1[16];
    {
        const int base = tile << 7;
        const int ge0 = (tile < ntiles) ? (base + m0 + g) : E;
        gather_row(gth0, PA, PB, idxA, idxB, ge0, E, t);
        const int ge1 = (tile < ntiles) ? (base + m0 + g + 8) : E;
        gather_row(gth1, PA, PB, idxA, idxB, ge1, E, t);
    }
    __syncthreads();   // weights + Xc(tile0) ready

    for (; tile < ntiles; tile += gridDim.x) {
        const int base = tile << 7;
        const int ntile = tile + gridDim.x;
        const bool npv = (ntile < ntiles);

        // ---- prefetch next tile's ef into registers -----------------------
        float4 pf[8];
        {
            const int nge = (ntile << 7) + sr;
            if (npv && nge < E) {
                const float4* s = (const float4*)(EF + (size_t)nge * HD);
                #pragma unroll
                for (int j = 0; j < 4; j++) {
                    const int c = half * 4 + j;
                    pf[2 * j]     = s[2 * c];
                    pf[2 * j + 1] = s[2 * c + 1];
                }
            }
        }

        // ---- GEMM1: 16e x 128h, K=64 (4 k16 steps, 16 n-chunks) ----
        float c1[16][4];
        #pragma unroll
        for (int ni = 0; ni < 16; ni++)
            #pragma unroll
            for (int p = 0; p < 4; p++) c1[ni][p] = 0.0f;

        #pragma unroll
        for (int ks = 0; ks < 4; ks++) {
            const int C0 = 2 * ks, C1 = 2 * ks + 1;
            const int o0 = ((C0 & ~7) << 2) + off3[C0 & 7];
            const int o1 = ((C1 & ~7) << 2) + off3[C1 & 7];
            const uint32_t a0 = Xc[arA0 + o0], a1 = Xc[arA1 + o0];
            const uint32_t a2 = Xc[arA0 + o1], a3 = Xc[arA1 + o1];
            #pragma unroll
            for (int ni = 0; ni < 16; ni++)
                mma16(c1[ni], a0, a1, a2, a3,
                      W1s[brB[ni] + o0], W1s[brB[ni] + o1]);
        }

        // ---- in-register epilogue 1: relu(c1 + gathered) -> A fragments ---
        // D-layout: thread (g,t) row g holds cols {ni*8+2t, ni*8+2t+1} in
        // c1[ni][0..1], row g+8 in c1[ni][2..3]. A-fragment for GEMM2 step ks
        // needs halves (k=16ks+2t, 16ks+2t+1) [a0/a1] and (+8) [a2/a3]:
        // exactly ah{0,1}[2ks] and ah{0,1}[2ks+1].
        uint32_t ah0[16], ah1[16];
        #pragma unroll
        for (int ni = 0; ni < 16; ni++) {
            const __half2 g0 = *(__half2*)&gth0[ni];
            const __half2 g1 = *(__half2*)&gth1[ni];
            ah0[ni] = p2h(fmaxf(c1[ni][0] + __low2float(g0), 0.0f),
                          fmaxf(c1[ni][1] + __high2float(g0), 0.0f));
            ah1[ni] = p2h(fmaxf(c1[ni][2] + __low2float(g1), 0.0f),
                          fmaxf(c1[ni][3] + __high2float(g1), 0.0f));
        }

        // ---- load next tile's gather (hidden under GEMM2) -----------------
        if (npv) {
            const int nb = ntile << 7;
            gather_row(gth0, PA, PB, idxA, idxB, nb + m0 + g, E, t);
            gather_row(gth1, PA, PB, idxA, idxB, nb + m0 + g + 8, E, t);
        }

        // ---- GEMM2: 16e x 64o, K=128 (8 k16 steps), A from registers ----
        float c2[8][4];
        #pragma unroll
        for (int ni = 0; ni < 8; ni++)
            #pragma unroll
            for (int p = 0; p < 4; p++) c2[ni][p] = 0.0f;

        #pragma unroll
        for (int ks = 0; ks < 8; ks++) {
            const int C0 = 2 * ks, C1 = 2 * ks + 1;
            const int o0 = ((C0 & ~7) << 2) + off3[C0 & 7];
            const int o1 = ((C1 & ~7) << 2) + off3[C1 & 7];
            const uint32_t a0 = ah0[2 * ks],     a1 = ah1[2 * ks];
            const uint32_t a2 = ah0[2 * ks + 1], a3 = ah1[2 * ks + 1];
            #pragma unroll
            for (int ni = 0; ni < 8; ni++)
                mma16(c2[ni], a0, a1, a2, a3,
                      W2s[br2[ni] + o0], W2s[br2[ni] + o1]);
        }

        // ---- deg + epilogue 2: + b2, atomic scatter ----
        if (deg != nullptr && tid < 128) {
            const int ge = base + tid;
            if (ge < E) atomicAdd(deg + idxA[ge], 1.0f);
        }
        {
            const int ge0 = base + m0 + g, ge1 = ge0 + 8;
            const int d0 = (ge0 < E) ? idxOut[ge0] : -1;
            const int d1 = (ge1 < E) ? idxOut[ge1] : -1;
            #pragma unroll
            for (int ni = 0; ni < 8; ni++) {
                const int col = ni * 8 + 2 * t;
                const float2 bb = *(const float2*)(sB2 + col);
                if (d0 >= 0) {
                    float* p = accum + (size_t)d0 * HD + col;
                    atomicAdd(p,     c2[ni][0] + bb.x);
                    atomicAdd(p + 1, c2[ni][1] + bb.y);
                }
                if (d1 >= 0) {
                    float* p = accum + (size_t)d1 * HD + col;
                    atomicAdd(p,     c2[ni][2] + bb.x);
                    atomicAdd(p + 1, c2[ni][3] + bb.y);
                }
            }
        }

        // ---- store prefetched ef into other buffer, swap, barrier ----
        if (npv) {
            const int nge = (ntile << 7) + sr;
            if (nge < E) {
                #pragma unroll
                for (int j = 0; j < 4; j++) {
                    const int c = half * 4 + j;
                    st_chunk(Xn, sr, 32, c, pack8(pf[2 * j], pf[2 * j + 1]));
                }
            }
        }
        uint32_t* tmp = Xc; Xc = Xn; Xn = tmp;
        __syncthreads();   // next Xc visible; prior Xc reads all done
    }
}

// ---------------------------------------------------------------------------
// Node MLP (unchanged, proven): x=[self, msum*scale](128)->relu(@W1+b1)(64)
//           -> @W2+b2 (64) -> direct store. 2 CTAs/SM.
// ---------------------------------------------------------------------------
__global__ void __launch_bounds__(NTPB, 2) node_mlp_tc(
    const float* __restrict__ selfF, const float* __restrict__ msum,
    const float* __restrict__ deg, const int* __restrict__ Sp,
    const float* __restrict__ W1, const float* __restrict__ b1,
    const float* __restrict__ W2, const float* __restrict__ b2,
    float* __restrict__ out, int N)
{
    extern __shared__ uint32_t smu[];
    uint32_t* W1s = smu + NW1_OFF;
    uint32_t* W2s = smu + NW2_OFF;
    uint32_t* Xs  = smu + NX_OFF;
    uint32_t* Hs  = smu + NH_OFF;
    float* sB1 = (float*)(smu + NB1_OFF);
    float* sB2 = (float*)(smu + NB2_OFF);

    const int tid = threadIdx.x;
    const int warp = tid >> 5, lane = tid & 31;
    const int g = lane >> 2, t = lane & 3;

    for (int i = tid; i < 64 * 64; i += NTPB) {
        const int kp = i >> 6, n = i & 63;
        const int ch = kp >> 2;
        const int cc = (ch & ~7) | ((ch & 7) ^ (n & 7));
        W1s[n * 64 + cc * 4 + (kp & 3)] =
            p2h(W1[(2 * kp) * 64 + n], W1[(2 * kp + 1) * 64 + n]);
    }
    for (int i = tid; i < 32 * 64; i += NTPB) {
        const int kp = i >> 6, n = i & 63;
        const int ch = kp >> 2;
        const int cc = (ch & ~7) | ((ch & 7) ^ (n & 7));
        W2s[n * 32 + cc * 4 + (kp & 3)] =
            p2h(W2[(2 * kp) * 64 + n], W2[(2 * kp + 1) * 64 + n]);
    }
    if (tid < 64) { sB1[tid] = b1[tid]; sB2[tid] = b2[tid]; }
    __syncthreads();

    const float invS = (Sp != nullptr) ? (1.0f / (float)(*Sp)) : 0.0f;

    int off3[8];
    #pragma unroll
    for (int c = 0; c < 8; c++) off3[c] = ((c ^ g) << 2) + t;

    const int m0 = (warp >> 1) * 32;
    const int n0 = (warp & 1) * 32;

    int arX[2][2], arH[2][2], brB[4], br2[4];
    #pragma unroll
    for (int mi = 0; mi < 2; mi++) {
        arX[mi][0] = (m0 + mi * 16 + g) * 64;
        arX[mi][1] = (m0 + mi * 16 + g + 8) * 64;
        arH[mi][0] = (m0 + mi * 16 + g) * 32;
        arH[mi][1] = (m0 + mi * 16 + g + 8) * 32;
    }
    #pragma unroll
    for (int ni = 0; ni < 4; ni++) {
        brB[ni] = (n0 + ni * 8 + g) * 64;
        br2[ni] = (n0 + ni * 8 + g) * 32;
    }

    const int sr = tid >> 1, half = tid & 1;
    const int ntiles = (N + 127) >> 7;

    for (int tile = blockIdx.x; tile < ntiles; tile += gridDim.x) {
        const int base = tile << 7;
        {
            const int i = base + sr;
            if (i < N) {
                if (half == 0) {
                    const float4* s = (const float4*)(selfF + (size_t)i * HD);
                    #pragma unroll
                    for (int j = 0; j < 8; j++)
                        st_chunk(Xs, sr, 64, j, pack8(s[2 * j], s[2 * j + 1]));
                } else {
                    const float sc = (Sp != nullptr) ? invS
                                                     : (1.0f / fmaxf(deg[i], 1.0f));
                    const float4* m = (const float4*)(msum + (size_t)i * HD);
                    #pragma unroll
                    for (int j = 0; j < 8; j++) {
                        float4 v0 = m[2 * j], v1 = m[2 * j + 1];
                        v0.x *= sc; v0.y *= sc; v0.z *= sc; v0.w *= sc;
                        v1.x *= sc; v1.y *= sc; v1.z *= sc; v1.w *= sc;
                        st_chunk(Xs, sr, 64, 8 + j, pack8(v0, v1));
                    }
                }
            }
        }
        __syncthreads();

        float c1[2][4][4];
        #pragma unroll
        for (int mi = 0; mi < 2; mi++)
            #pragma unroll
            for (int ni = 0; ni < 4; ni++)
                #pragma unroll
                for (int p = 0; p < 4; p++) c1[mi][ni][p] = 0.0f;

        #pragma unroll
        for (int ks = 0; ks < 8; ks++) {
            const int C0 = 2 * ks, C1 = 2 * ks + 1;
            const int o0 = ((C0 & ~7) << 2) + off3[C0 & 7];
            const int o1 = ((C1 & ~7) << 2) + off3[C1 & 7];
            uint32_t a[2][4];
            #pragma unroll
            for (int mi = 0; mi < 2; mi++) {
                a[mi][0] = Xs[arX[mi][0] + o0];
                a[mi][1] = Xs[arX[mi][1] + o0];
                a[mi][2] = Xs[arX[mi][0] + o1];
                a[mi][3] = Xs[arX[mi][1] + o1];
            }
            uint32_t b[4][2];
            #pragma unroll
            for (int ni = 0; ni < 4; ni++) {
                b[ni][0] = W1s[brB[ni] + o0];
                b[ni][1] = W1s[brB[ni] + o1];
            }
            #pragma unroll
            for (int mi = 0; mi < 2; mi++)
                #pragma unroll
                for (int ni = 0; ni < 4; ni++)
                    mma16(c1[mi][ni], a[mi][0], a[mi][1], a[mi][2], a[mi][3],
                          b[ni][0], b[ni][1]);
        }

        #pragma unroll
        for (int mi = 0; mi < 2; mi++) {
            const int r0 = m0 + mi * 16 + g;
            #pragma unroll
            for (int ni = 0; ni < 4; ni++) {
                const int col = n0 + ni * 8 + 2 * t;
                const float2 bb = *(const float2*)(sB1 + col);
                const int ch = (n0 >> 3) + ni;
                const int cc = (ch & ~7) | ((ch & 7) ^ g);
                const int wo = cc * 4 + t;
                Hs[r0 * 32 + wo] =
                    p2h(fmaxf(c1[mi][ni][0] + bb.x, 0.0f),
                        fmaxf(c1[mi][ni][1] + bb.y, 0.0f));
                Hs[(r0 + 8) * 32 + wo] =
                    p2h(fmaxf(c1[mi][ni][2] + bb.x, 0.0f),
                        fmaxf(c1[mi][ni][3] + bb.y, 0.0f));
            }
        }
        __syncthreads();

        float c2[2][4][4];
        #pragma unroll
        for (int mi = 0; mi < 2; mi++)
            #pragma unroll
            for (int ni = 0; ni < 4; ni++)
                #pragma unroll
                for (int p = 0; p < 4; p++) c2[mi][ni][p] = 0.0f;

        #pragma unroll
        for (int ks = 0; ks < 4; ks++) {
            const int C0 = 2 * ks, C1 = 2 * ks + 1;
            const int o0 = ((C0 & ~7) << 2) + off3[C0 & 7];
            const int o1 = ((C1 & ~7) << 2) + off3[C1 & 7];
            uint32_t a[2][4];
            #pragma unroll
            for (int mi = 0; mi < 2; mi++) {
                a[mi][0] = Hs[arH[mi][0] + o0];
                a[mi][1] = Hs[arH[mi][1] + o0];
                a[mi][2] = Hs[arH[mi][0] + o1];
                a[mi][3] = Hs[arH[mi][1] + o1];
            }
            uint32_t b[4][2];
            #pragma unroll
            for (int ni = 0; ni < 4; ni++) {
                b[ni][0] = W2s[br2[ni] + o0];
                b[ni][1] = W2s[br2[ni] + o1];
            }
            #pragma unroll
            for (int mi = 0; mi < 2; mi++)
                #pragma unroll
                for (int ni = 0; ni < 4; ni++)
                    mma16(c2[mi][ni], a[mi][0], a[mi][1], a[mi][2], a[mi][3],
                          b[ni][0], b[ni][1]);
        }

        #pragma unroll
        for (int mi = 0; mi < 2; mi++) {
            const int r0 = m0 + mi * 16 + g;
            const int gi0 = base + r0, gi1 = gi0 + 8;
            #pragma unroll
            for (int ni = 0; ni < 4; ni++) {
                const int col = n0 + ni * 8 + 2 * t;
                const float2 bb = *(const float2*)(sB2 + col);
                if (gi0 < N)
                    *(float2*)(out + (size_t)gi0 * HD + col) =
                        make_float2(c2[mi][ni][0] + bb.x, c2[mi][ni][1] + bb.y);
                if (gi1 < N)
                    *(float2*)(out + (size_t)gi1 * HD + col) =
                        make_float2(c2[mi][ni][2] + bb.x, c2[mi][ni][3] + bb.y);
            }
        }
        __syncthreads();
    }
}

// ---------------------------------------------------------------------------
extern "C" void kernel_launch(void* const* d_in, const int* in_sizes, int n_in,
                              void* d_out, int out_size)
{
    const float* h_v    = (const float*)d_in[0];
    const float* h_u    = (const float*)d_in[1];
    const float* e_feat = (const float*)d_in[2];
    const int*   ei     = (const int*)d_in[3];
    const int*   Sp     = (const int*)d_in[4];
    const float* a2u_w1 = (const float*)d_in[5];
    const float* a2u_b1 = (const float*)d_in[6];
    const float* a2u_w2 = (const float*)d_in[7];
    const float* a2u_b2 = (const float*)d_in[8];
    const float* u_w1   = (const float*)d_in[9];
    const float* u_b1   = (const float*)d_in[10];
    const float* u_w2   = (const float*)d_in[11];
    const float* u_b2   = (const float*)d_in[12];
    const float* u2a_w1 = (const float*)d_in[13];
    const float* u2a_b1 = (const float*)d_in[14];
    const float* u2a_w2 = (const float*)d_in[15];
    const float* u2a_b2 = (const float*)d_in[16];
    const float* a_w1   = (const float*)d_in[17];
    const float* a_b1   = (const float*)d_in[18];
    const float* a_w2   = (const float*)d_in[19];
    const float* a_b2   = (const float*)d_in[20];

    const int NVn = in_sizes[0] / HD;
    const int NUn = in_sizes[1] / HD;
    const int E   = in_sizes[3] / 2;
    const int* src = ei;
    const int* dst = ei + E;

    float *m_u = nullptr, *m_v = nullptr, *degp = nullptr;
    uint32_t *pA = nullptr, *pB = nullptr;
    cudaGetSymbolAddress((void**)&m_u, g_m_u);
    cudaGetSymbolAddress((void**)&m_v, g_m_v);
    cudaGetSymbolAddress((void**)&degp, g_deg);
    cudaGetSymbolAddress((void**)&pA, g_PA);
    cudaGetSymbolAddress((void**)&pB, g_PB);

    int sms = 148;
    cudaDeviceGetAttribute(&sms, cudaDevAttrMultiProcessorCount, 0);

    cudaFuncSetAttribute(edge_mlp_tc,
                         cudaFuncAttributeMaxDynamicSharedMemorySize, EDGE_SMEM);
    cudaFuncSetAttribute(node_mlp_tc,
                         cudaFuncAttributeMaxDynamicSharedMemorySize, NODE_SMEM);
    cudaFuncSetAttribute(pre2,
                         cudaFuncAttributeMaxDynamicSharedMemorySize, PRE_SMEM);

    cudaMemsetAsync(m_u,  0, (size_t)NUn * HD * sizeof(float));
    cudaMemsetAsync(m_v,  0, (size_t)NVn * HD * sizeof(float));
    cudaMemsetAsync(degp, 0, (size_t)NVn * sizeof(float));

    float* h_v_out = (float*)d_out;
    float* h_u_out = (float*)d_out + (size_t)NVn * HD;

    const int etiles = (E + 127) >> 7;
    const int egrid = etiles < sms ? etiles : sms;
    const int vt = (NVn + 127) >> 7, ut = (NUn + 127) >> 7;
    const int gA1 = vt < sms ? vt : sms;
    const int gB1 = ut < sms ? ut : sms;
    const int gA2 = ut < sms ? ut : sms;
    const int gB2 = vt < sms ? vt : sms;
    const int pg_u = ut < 2 * sms ? ut : 2 * sms;
    const int pg_v = vt < 2 * sms ? vt : 2 * sms;

    // ---- pass 1: fused precompute + edge + node u ----
    pre2<<<gA1 + gB1, PTPB, PRE_SMEM>>>(
        h_v, a2u_w1, a2u_b1, pA, NVn, gA1,
        h_u, a2u_w1 + 64 * 128, pB, NUn);

    edge_mlp_tc<<<egrid, ETPB, EDGE_SMEM>>>(
        pA, src, pB, dst, e_feat, dst,
        a2u_w1 + 128 * 128, a2u_w2, a2u_b2, m_u, degp, E);

    node_mlp_tc<<<pg_u, NTPB, NODE_SMEM>>>(
        h_u, m_u, nullptr, Sp,
        u_w1, u_b1, u_w2, u_b2, h_u_out, NUn);

    // ---- pass 2: fused precompute + edge + node v ----
    pre2<<<gA2 + gB2, PTPB, PRE_SMEM>>>(
        h_u_out, u2a_w1, u2a_b1, pA, NUn, gA2,
        h_v, u2a_w1 + 64 * 128, pB, NVn);

    edge_mlp_tc<<<egrid, ETPB, EDGE_SMEM>>>(
        pA, dst, pB, src, e_feat, src,
        u2a_w1 + 128 * 128, u2a_w2, u2a_b2, m_v, nullptr, E);

    node_mlp_tc<<<pg_v, NTPB, NODE_SMEM>>>(
        h_v, m_v, degp, nullptr,
        a_w1, a_b1, a_w2, a_b2, h_v_out, NVn);
}